// round 9
// baseline (speedup 1.0000x reference)
#include <cuda_runtime.h>

#define H 4096
#define NIN 17
#define NA 4
#define BW 2048             // column band width (2 bands)
#define NPART 512           // partials per column per band

// persistent device scratch (static globals allowed; no runtime alloc)
__device__ float4 g_scratch4[NPART * BW / 4];  // 4 MiB, reused across bands
__device__ __align__(16) float g_h[H];         // aligned shadow of h

// ---- 256-bit L2-eviction-hinted loads (sm_100+: hints require .v4.b64/.v8.b32) ----
__device__ __forceinline__ void ldg8_ef(const float* p, float v[8]) {
    unsigned long long r0, r1, r2, r3;
    asm volatile("ld.global.L2::evict_first.v4.b64 {%0,%1,%2,%3}, [%4];"
                 : "=l"(r0), "=l"(r1), "=l"(r2), "=l"(r3) : "l"(p));
    v[0] = __uint_as_float((unsigned)r0); v[1] = __uint_as_float((unsigned)(r0 >> 32));
    v[2] = __uint_as_float((unsigned)r1); v[3] = __uint_as_float((unsigned)(r1 >> 32));
    v[4] = __uint_as_float((unsigned)r2); v[5] = __uint_as_float((unsigned)(r2 >> 32));
    v[6] = __uint_as_float((unsigned)r3); v[7] = __uint_as_float((unsigned)(r3 >> 32));
}
__device__ __forceinline__ void ldg8_el(const float* p, float v[8]) {
    unsigned long long r0, r1, r2, r3;
    asm volatile("ld.global.L2::evict_last.v4.b64 {%0,%1,%2,%3}, [%4];"
                 : "=l"(r0), "=l"(r1), "=l"(r2), "=l"(r3) : "l"(p));
    v[0] = __uint_as_float((unsigned)r0); v[1] = __uint_as_float((unsigned)(r0 >> 32));
    v[2] = __uint_as_float((unsigned)r1); v[3] = __uint_as_float((unsigned)(r1 >> 32));
    v[4] = __uint_as_float((unsigned)r2); v[5] = __uint_as_float((unsigned)(r2 >> 32));
    v[6] = __uint_as_float((unsigned)r3); v[7] = __uint_as_float((unsigned)(r3 >> 32));
}

// ===== K1_b: partial sums over a 2048-col band; 16 rows x 2048 cols per block =====
__global__ __launch_bounds__(512)
void k1_partials(const float* __restrict__ hidden,
                 const float* __restrict__ w,
                 const float* __restrict__ alpha,
                 const float* __restrict__ hebb,
                 int band)
{
    const int tid = threadIdx.x;
    const int q   = tid & 255;         // col chunk (8 cols)
    const int g   = tid >> 8;          // row group 0..1
    const int i0  = blockIdx.x * 16 + g * 8;
    const int c0  = band * BW + q * 8;

    float acc[8] = {0.f, 0.f, 0.f, 0.f, 0.f, 0.f, 0.f, 0.f};
    #pragma unroll
    for (int r = 0; r < 8; ++r) {
        const float hv = __ldg(&hidden[i0 + r]);
        const size_t off = (size_t)(i0 + r) * H + c0;
        float wv[8], av[8], hb[8];
        ldg8_ef(w     + off, wv);
        ldg8_ef(alpha + off, av);
        ldg8_el(hebb  + off, hb);      // short reuse distance to K3_b
        #pragma unroll
        for (int c = 0; c < 8; ++c)
            acc[c] = fmaf(hv, fmaf(av[c], hb[c], wv[c]), acc[c]);
    }
    const int P = blockIdx.x * 2 + g;  // partial row 0..511
    float4* s = &g_scratch4[(P * BW + q * 8) / 4];
    s[0] = make_float4(acc[0], acc[1], acc[2], acc[3]);
    s[1] = make_float4(acc[4], acc[5], acc[6], acc[7]);
}

// ===== K2_b: reduce 512 partials per column, i2h + tanh -> h (band cols) =====
__global__ __launch_bounds__(512)
void k2_reduce(const float* __restrict__ x,
               const float* __restrict__ i2h_w,
               const float* __restrict__ i2h_b,
               float* __restrict__ out,
               int band)
{
    __shared__ float4 sred[64][8];
    const int tid   = threadIdx.x;
    const int q     = tid & 7;          // local quad (4 cols): 8 quads = 32 cols
    const int s     = tid >> 3;         // slice 0..63
    const int qbase = blockIdx.x * 8;   // band-local quad base

    float4 acc = make_float4(0.f, 0.f, 0.f, 0.f);
    #pragma unroll
    for (int p = s; p < NPART; p += 64) {
        const float4 v = __ldcs(&g_scratch4[p * (BW / 4) + qbase + q]);
        acc.x += v.x; acc.y += v.y; acc.z += v.z; acc.w += v.w;
    }
    sred[s][q] = acc;
    __syncthreads();

    if (tid < 8) {
        float4 pre = sred[0][tid];
        #pragma unroll
        for (int t = 1; t < 64; ++t) {
            const float4 v = sred[t][tid];
            pre.x += v.x; pre.y += v.y; pre.z += v.z; pre.w += v.w;
        }
        const int j0 = band * BW + (qbase + tid) * 4;
        const float* prep = &pre.x;
        #pragma unroll
        for (int c = 0; c < 4; ++c) {
            const int j = j0 + c;
            float pr = i2h_b[j];
            #pragma unroll
            for (int kk = 0; kk < NIN; ++kk)
                pr = fmaf(x[kk], i2h_w[j * NIN + kk], pr);
            const float hj = tanhf(pr + prep[c]);
            out[5 + j] = hj;
            g_h[j]     = hj;
        }
    }
}

// ===== K3_b: hebb_new for band cols; block 512 (last launch) = heads =====
__global__ __launch_bounds__(512)
void k3_hebb(const float* __restrict__ hebb,
             const float* __restrict__ hidden,
             const float* __restrict__ eta,
             const float* __restrict__ h2o_w,
             const float* __restrict__ h2o_b,
             const float* __restrict__ h2v_w,
             const float* __restrict__ h2v_b,
             float* __restrict__ out,
             int band)
{
    const int tid = threadIdx.x;

    if (blockIdx.x == 512) {
        // ----- heads (only present on final launch): 5 dots + softmax -----
        __shared__ float red[16][NA + 1];
        __shared__ float logits[NA + 1];
        const int warp = tid >> 5, lane = tid & 31;
        float acc[NA + 1] = {0.f, 0.f, 0.f, 0.f, 0.f};
        #pragma unroll
        for (int k = 0; k < H / 512; ++k) {
            const int j = tid + k * 512;
            const float hv = g_h[j];
            acc[0] = fmaf(hv, h2o_w[0 * H + j], acc[0]);
            acc[1] = fmaf(hv, h2o_w[1 * H + j], acc[1]);
            acc[2] = fmaf(hv, h2o_w[2 * H + j], acc[2]);
            acc[3] = fmaf(hv, h2o_w[3 * H + j], acc[3]);
            acc[4] = fmaf(hv, h2v_w[j],         acc[4]);
        }
        #pragma unroll
        for (int a = 0; a < NA + 1; ++a) {
            #pragma unroll
            for (int o = 16; o; o >>= 1)
                acc[a] += __shfl_xor_sync(0xffffffffu, acc[a], o);
            if (lane == 0) red[warp][a] = acc[a];
        }
        __syncthreads();
        if (tid < NA + 1) {
            float s = (tid < NA) ? h2o_b[tid] : h2v_b[0];
            #pragma unroll
            for (int wp = 0; wp < 16; ++wp) s += red[wp][tid];
            logits[tid] = s;
        }
        __syncthreads();
        if (tid == 0) {
            float m = logits[0];
            #pragma unroll
            for (int a = 1; a < NA; ++a) m = fmaxf(m, logits[a]);
            float e[NA], se = 0.f;
            #pragma unroll
            for (int a = 0; a < NA; ++a) { e[a] = expf(logits[a] - m); se += e[a]; }
            const float inv = 1.f / se;
            #pragma unroll
            for (int a = 0; a < NA; ++a) out[a] = e[a] * inv;
            out[NA] = logits[NA];
        }
        return;
    }

    // ----- hebb update for this band: reversed block order (L2-hottest rows first) -----
    const size_t base = (size_t)(511 - blockIdx.x) * 16384;   // band-local element base
    const float eta_v = __ldg(eta);
    const float om    = 1.f - eta_v;
    float* __restrict__ outp = out + 5 + H;    // 4B-misaligned -> scalar stores

    #pragma unroll 8
    for (int k = 0; k < 32; ++k) {
        const size_t n = base + (size_t)k * 512 + tid;
        const int i  = (int)(n >> 11);            // band-local row
        const int j  = band * BW + (int)(n & (BW - 1));
        const size_t idx = (size_t)i * H + j;
        const float hb = __ldg(hebb + idx);       // should be L2-resident now
        __stcs(outp + idx, fmaf(om, hb, eta_v * __ldg(&hidden[i]) * g_h[j]));
    }
}

extern "C" void kernel_launch(void* const* d_in, const int* in_sizes, int n_in,
                              void* d_out, int out_size)
{
    const float* x      = (const float*)d_in[0];
    const float* hidden = (const float*)d_in[1];
    const float* hebb   = (const float*)d_in[2];
    const float* i2h_w  = (const float*)d_in[3];
    const float* i2h_b  = (const float*)d_in[4];
    const float* w      = (const float*)d_in[5];
    const float* alpha  = (const float*)d_in[6];
    const float* eta    = (const float*)d_in[7];
    const float* h2o_w  = (const float*)d_in[8];
    const float* h2o_b  = (const float*)d_in[9];
    const float* h2v_w  = (const float*)d_in[10];
    const float* h2v_b  = (const float*)d_in[11];
    float* out = (float*)d_out;

    // band 0
    k1_partials<<<256, 512>>>(hidden, w, alpha, hebb, 0);
    k2_reduce  <<< 64, 512>>>(x, i2h_w, i2h_b, out, 0);
    k3_hebb    <<<512, 512>>>(hebb, hidden, eta, h2o_w, h2o_b, h2v_w, h2v_b, out, 0);
    // band 1 (+ head block)
    k1_partials<<<256, 512>>>(hidden, w, alpha, hebb, 1);
    k2_reduce  <<< 64, 512>>>(x, i2h_w, i2h_b, out, 1);
    k3_hebb    <<<513, 512>>>(hebb, hidden, eta, h2o_w, h2o_b, h2v_w, h2v_b, out, 1);
}

// round 10
// speedup vs baseline: 1.2159x; 1.2159x over previous
#include <cuda_runtime.h>
#include <cooperative_groups.h>
namespace cg = cooperative_groups;

#define H 4096
#define NIN 17
#define NA 4
#define COLS 32            // columns per cluster (full 128B line)
#define ROWS 1024          // rows per CTA (cluster of 4 covers 4096)
#define T 512
#define STRIDE 36          // padded smem row stride in floats (kills bank conflicts)

// smem layout (dynamic):
#define OFF_HEBB   0
#define OFF_HIDDEN (ROWS * STRIDE)                 // + ROWS
#define OFF_RED    (OFF_HIDDEN + ROWS)             // + 16*32
#define OFF_CROSS  (OFF_RED + 16 * 32)             // + 4*32
#define OFF_HV     (OFF_CROSS + 4 * 32)            // + 32
#define SMEM_FLOATS (OFF_HV + 32)

__device__ __align__(16) float g_h[H];
__device__ float g_logits[NA + 1];

// 256-bit load (two 128b halves packed in .v4.b64)
__device__ __forceinline__ void ldg8(const float* p, float v[8]) {
    unsigned long long r0, r1, r2, r3;
    asm volatile("ld.global.nc.v4.b64 {%0,%1,%2,%3}, [%4];"
                 : "=l"(r0), "=l"(r1), "=l"(r2), "=l"(r3) : "l"(p));
    v[0] = __uint_as_float((unsigned)r0); v[1] = __uint_as_float((unsigned)(r0 >> 32));
    v[2] = __uint_as_float((unsigned)r1); v[3] = __uint_as_float((unsigned)(r1 >> 32));
    v[4] = __uint_as_float((unsigned)r2); v[5] = __uint_as_float((unsigned)(r2 >> 32));
    v[6] = __uint_as_float((unsigned)r3); v[7] = __uint_as_float((unsigned)(r3 >> 32));
}

__global__ void __cluster_dims__(4, 1, 1) __launch_bounds__(T, 1)
fused_cluster(const float* __restrict__ x,
              const float* __restrict__ hidden,
              const float* __restrict__ hebb,
              const float* __restrict__ i2h_w,
              const float* __restrict__ i2h_b,
              const float* __restrict__ w,
              const float* __restrict__ alpha,
              const float* __restrict__ eta,
              float* __restrict__ out)
{
    extern __shared__ float sh[];
    float* sh_hebb   = sh + OFF_HEBB;
    float* sh_hidden = sh + OFF_HIDDEN;
    float* sh_red    = sh + OFF_RED;
    float* sh_cross  = sh + OFF_CROSS;
    float* sh_hv     = sh + OFF_HV;

    cg::cluster_group cluster = cg::this_cluster();
    const unsigned rank = cluster.block_rank();

    const int tid  = threadIdx.x;
    const int q    = tid & 3;          // col chunk (8 cols)
    const int rloc = tid >> 2;         // 0..127
    const int warp = tid >> 5;
    const int lane = tid & 31;
    const int jb   = (blockIdx.x >> 2) * COLS;   // cluster column base
    const int i0   = (int)rank * ROWS;           // this CTA's row base
    const float eta_v = __ldg(eta);

    // preamble: this CTA's hidden slice
    sh_hidden[tid]       = hidden[i0 + tid];
    sh_hidden[tid + 512] = hidden[i0 + tid + 512];
    __syncthreads();

    // ---- Phase 1: stream w/alpha/hebb quadrant; stash hebb in SMEM; partials ----
    float acc[8] = {0.f, 0.f, 0.f, 0.f, 0.f, 0.f, 0.f, 0.f};
    #pragma unroll 2
    for (int pass = 0; pass < ROWS / 128; ++pass) {
        const int il = rloc + pass * 128;
        const size_t off = (size_t)(i0 + il) * H + jb + q * 8;
        float wv[8], av[8], hb[8];
        ldg8(w     + off, wv);
        ldg8(alpha + off, av);
        ldg8(hebb  + off, hb);
        float4* s = (float4*)&sh_hebb[il * STRIDE + q * 8];
        s[0] = make_float4(hb[0], hb[1], hb[2], hb[3]);
        s[1] = make_float4(hb[4], hb[5], hb[6], hb[7]);
        const float hv = sh_hidden[il];
        #pragma unroll
        for (int c = 0; c < 8; ++c)
            acc[c] = fmaf(hv, fmaf(av[c], hb[c], wv[c]), acc[c]);
    }
    // warp reduce over row lanes (xor 4/8/16 keeps q = lane&3)
    #pragma unroll
    for (int o = 4; o <= 16; o <<= 1)
        #pragma unroll
        for (int c = 0; c < 8; ++c)
            acc[c] += __shfl_xor_sync(0xffffffffu, acc[c], o);
    if (lane < 4) {
        #pragma unroll
        for (int c = 0; c < 8; ++c)
            sh_red[warp * 32 + lane * 8 + c] = acc[c];
    }
    __syncthreads();

    // CTA partial per column -> leader's sh_cross via DSMEM
    if (tid < COLS) {
        float s = 0.f;
        #pragma unroll
        for (int wp = 0; wp < 16; ++wp) s += sh_red[wp * 32 + tid];
        float* dst = cluster.map_shared_rank(sh_cross, 0);
        dst[rank * COLS + tid] = s;
    }
    cluster.sync();

    // leader: final reduce + i2h + tanh -> h
    if (rank == 0 && tid < COLS) {
        float s = sh_cross[tid] + sh_cross[COLS + tid]
                + sh_cross[2 * COLS + tid] + sh_cross[3 * COLS + tid];
        const int j = jb + tid;
        float pr = i2h_b[j];
        #pragma unroll
        for (int kk = 0; kk < NIN; ++kk)
            pr = fmaf(x[kk], i2h_w[j * NIN + kk], pr);
        const float hj = tanhf(pr + s);
        g_h[j]     = hj;
        out[5 + j] = hj;
        sh_hv[tid] = hj;
    }
    cluster.sync();

    // broadcast h back to every CTA's smem
    if (tid < COLS) {
        const float* src = cluster.map_shared_rank(sh_hv, 0);
        sh_hv[tid] = src[tid];
    }
    __syncthreads();

    // ---- Phase 3: hebb_new from SMEM stash (no gmem re-read) ----
    const float om = 1.f - eta_v;
    const int  c3  = tid & 31;         // column (warp = 32 consecutive cols = 128B)
    const int  r3  = tid >> 5;         // 0..15 row lane
    const float hj = sh_hv[c3];
    float* __restrict__ outp = out + 5 + H;     // 4B-misaligned -> scalar stores

    #pragma unroll 8
    for (int it = 0; it < ROWS / 16; ++it) {
        const int il = r3 + it * 16;
        const float hb = sh_hebb[il * STRIDE + c3];
        const size_t idx = (size_t)(i0 + il) * H + jb + c3;
        __stcs(outp + idx, fmaf(om, hb, eta_v * sh_hidden[il] * hj));
    }
}

// ---- heads: 5 blocks, one logit each (fixed-order deterministic reduce) ----
__global__ __launch_bounds__(512)
void k_heads(const float* __restrict__ h2o_w,
             const float* __restrict__ h2o_b,
             const float* __restrict__ h2v_w,
             const float* __restrict__ h2v_b)
{
    __shared__ float red[16];
    const int a = blockIdx.x;
    const int tid = threadIdx.x, warp = tid >> 5, lane = tid & 31;
    const float* row = (a < NA) ? (h2o_w + (size_t)a * H) : h2v_w;
    float s = 0.f;
    #pragma unroll
    for (int k = 0; k < H / 512; ++k) {
        const int j = tid + k * 512;
        s = fmaf(g_h[j], row[j], s);
    }
    #pragma unroll
    for (int o = 16; o; o >>= 1) s += __shfl_xor_sync(0xffffffffu, s, o);
    if (lane == 0) red[warp] = s;
    __syncthreads();
    if (tid == 0) {
        float t = (a < NA) ? h2o_b[a] : h2v_b[0];
        #pragma unroll
        for (int wp = 0; wp < 16; ++wp) t += red[wp];
        g_logits[a] = t;
    }
}

// ---- finisher: softmax + value ----
__global__ void k_fin(float* __restrict__ out)
{
    if (threadIdx.x == 0) {
        float lg[NA];
        #pragma unroll
        for (int a = 0; a < NA; ++a) lg[a] = g_logits[a];
        float m = lg[0];
        #pragma unroll
        for (int a = 1; a < NA; ++a) m = fmaxf(m, lg[a]);
        float e[NA], se = 0.f;
        #pragma unroll
        for (int a = 0; a < NA; ++a) { e[a] = expf(lg[a] - m); se += e[a]; }
        const float inv = 1.f / se;
        #pragma unroll
        for (int a = 0; a < NA; ++a) out[a] = e[a] * inv;
        out[NA] = g_logits[NA];
    }
}

extern "C" void kernel_launch(void* const* d_in, const int* in_sizes, int n_in,
                              void* d_out, int out_size)
{
    const float* x      = (const float*)d_in[0];
    const float* hidden = (const float*)d_in[1];
    const float* hebb   = (const float*)d_in[2];
    const float* i2h_w  = (const float*)d_in[3];
    const float* i2h_b  = (const float*)d_in[4];
    const float* w      = (const float*)d_in[5];
    const float* alpha  = (const float*)d_in[6];
    const float* eta    = (const float*)d_in[7];
    const float* h2o_w  = (const float*)d_in[8];
    const float* h2o_b  = (const float*)d_in[9];
    const float* h2v_w  = (const float*)d_in[10];
    const float* h2v_b  = (const float*)d_in[11];
    float* out = (float*)d_out;

    const size_t smem = SMEM_FLOATS * sizeof(float);   // ~154 KB
    cudaFuncSetAttribute(fused_cluster,
                         cudaFuncAttributeMaxDynamicSharedMemorySize, (int)smem);

    fused_cluster<<<(H / COLS) * 4, T, smem>>>(x, hidden, hebb, i2h_w, i2h_b,
                                               w, alpha, eta, out);
    k_heads<<<NA + 1, 512>>>(h2o_w, h2o_b, h2v_w, h2v_b);
    k_fin<<<1, 32>>>(out);
}